// round 5
// baseline (speedup 1.0000x reference)
#include <cuda_runtime.h>
#include <cuda_bf16.h>
#include <math.h>
#include <stdint.h>

// Problem constants
#define S_LEN 2048
#define D_DIM 1024
#define H_NUM 16
#define HDIM  64
#define FF_DIM 4096
#define CCH   64
#define NCH   (S_LEN/CCH)

// ---------------- scratch (static device globals; no allocation) ----------
// fp32
__device__ float g_q   [S_LEN*D_DIM];
__device__ float g_k   [S_LEN*D_DIM];
__device__ float g_v   [S_LEN*D_DIM];
__device__ float g_x2  [S_LEN*D_DIM];
__device__ float g_kv  [H_NUM*NCH*HDIM*HDIM];
__device__ float g_kvp [H_NUM*NCH*HDIM*HDIM];
__device__ float g_zc  [H_NUM*NCH*HDIM];
__device__ float g_zp  [H_NUM*NCH*HDIM];
// bf16 split activations
__device__ __align__(16) __nv_bfloat16 g_h_hi   [S_LEN*D_DIM];
__device__ __align__(16) __nv_bfloat16 g_h_lo   [S_LEN*D_DIM];
__device__ __align__(16) __nv_bfloat16 g_h2_hi  [S_LEN*D_DIM];
__device__ __align__(16) __nv_bfloat16 g_h2_lo  [S_LEN*D_DIM];
__device__ __align__(16) __nv_bfloat16 g_at_hi  [S_LEN*D_DIM];
__device__ __align__(16) __nv_bfloat16 g_at_lo  [S_LEN*D_DIM];
__device__ __align__(16) __nv_bfloat16 g_ff_hi  [S_LEN*FF_DIM];
__device__ __align__(16) __nv_bfloat16 g_ff_lo  [S_LEN*FF_DIM];
// bf16 split weights
__device__ __align__(16) __nv_bfloat16 g_wq_hi[D_DIM*D_DIM], g_wq_lo[D_DIM*D_DIM];
__device__ __align__(16) __nv_bfloat16 g_wk_hi[D_DIM*D_DIM], g_wk_lo[D_DIM*D_DIM];
__device__ __align__(16) __nv_bfloat16 g_wv_hi[D_DIM*D_DIM], g_wv_lo[D_DIM*D_DIM];
__device__ __align__(16) __nv_bfloat16 g_wo_hi[D_DIM*D_DIM], g_wo_lo[D_DIM*D_DIM];
__device__ __align__(16) __nv_bfloat16 g_w1_hi[FF_DIM*D_DIM], g_w1_lo[FF_DIM*D_DIM];
__device__ __align__(16) __nv_bfloat16 g_w2_hi[D_DIM*FF_DIM], g_w2_lo[D_DIM*FF_DIM];

// ---------------- helpers ---------------------------------------------------
__device__ __forceinline__ uint2 cvt_hi_lo(float4 v, uint2& lo) {
    __nv_bfloat16 hx = __float2bfloat16(v.x);
    __nv_bfloat16 hy = __float2bfloat16(v.y);
    __nv_bfloat16 hz = __float2bfloat16(v.z);
    __nv_bfloat16 hw = __float2bfloat16(v.w);
    __nv_bfloat16 lx = __float2bfloat16(v.x - __bfloat162float(hx));
    __nv_bfloat16 ly = __float2bfloat16(v.y - __bfloat162float(hy));
    __nv_bfloat16 lz = __float2bfloat16(v.z - __bfloat162float(hz));
    __nv_bfloat16 lw = __float2bfloat16(v.w - __bfloat162float(hw));
    lo.x = (uint32_t)__bfloat16_as_ushort(lx) | ((uint32_t)__bfloat16_as_ushort(ly) << 16);
    lo.y = (uint32_t)__bfloat16_as_ushort(lz) | ((uint32_t)__bfloat16_as_ushort(lw) << 16);
    uint2 hi;
    hi.x = (uint32_t)__bfloat16_as_ushort(hx) | ((uint32_t)__bfloat16_as_ushort(hy) << 16);
    hi.y = (uint32_t)__bfloat16_as_ushort(hz) | ((uint32_t)__bfloat16_as_ushort(hw) << 16);
    return hi;
}

__device__ __forceinline__ void split2(float v, __nv_bfloat16& hi, __nv_bfloat16& lo) {
    hi = __float2bfloat16(v);
    lo = __float2bfloat16(v - __bfloat162float(hi));
}

// ---------------- elementwise fp32 -> bf16 hi/lo split ---------------------
__global__ void cvt_split(const float* __restrict__ src,
                          __nv_bfloat16* __restrict__ hi,
                          __nv_bfloat16* __restrict__ lo, int n) {
    int i = (blockIdx.x * 256 + threadIdx.x) * 4;
    if (i >= n) return;
    float4 v = *(const float4*)(src + i);
    uint2 l, h = cvt_hi_lo(v, l);
    *(uint2*)(hi + i) = h;
    *(uint2*)(lo + i) = l;
}

// ---------------- LayerNorm with split bf16 output --------------------------
__global__ void ln_split(const float* __restrict__ x,
                         const float* __restrict__ g,
                         const float* __restrict__ b,
                         __nv_bfloat16* __restrict__ ohi,
                         __nv_bfloat16* __restrict__ olo) {
    int row = blockIdx.x;
    const float* xr = x + (size_t)row * D_DIM;
    float s = 0.f, s2 = 0.f;
    for (int i = threadIdx.x; i < D_DIM; i += 256) {
        float v = xr[i];
        s += v; s2 += v * v;
    }
    __shared__ float sh[64];
    for (int off = 16; off > 0; off >>= 1) {
        s  += __shfl_down_sync(0xffffffffu, s,  off);
        s2 += __shfl_down_sync(0xffffffffu, s2, off);
    }
    int w = threadIdx.x >> 5, l = threadIdx.x & 31;
    if (l == 0) { sh[w] = s; sh[w + 32] = s2; }
    __syncthreads();
    if (threadIdx.x == 0) {
        float ts = 0.f, ts2 = 0.f;
        for (int i = 0; i < 8; i++) { ts += sh[i]; ts2 += sh[i + 32]; }
        float mu = ts / D_DIM;
        sh[0] = mu;
        sh[1] = rsqrtf(ts2 / D_DIM - mu * mu + 1e-5f);
    }
    __syncthreads();
    float mu = sh[0], rstd = sh[1];
    for (int i = threadIdx.x * 4; i < D_DIM; i += 256 * 4) {
        float4 xv = *(const float4*)(xr + i);
        float4 gv = *(const float4*)(g + i);
        float4 bv = *(const float4*)(b + i);
        float4 y;
        y.x = (xv.x - mu) * rstd * gv.x + bv.x;
        y.y = (xv.y - mu) * rstd * gv.y + bv.y;
        y.z = (xv.z - mu) * rstd * gv.z + bv.z;
        y.w = (xv.w - mu) * rstd * gv.w + bv.w;
        uint2 lo, hi = cvt_hi_lo(y, lo);
        *(uint2*)(ohi + (size_t)row * D_DIM + i) = hi;
        *(uint2*)(olo + (size_t)row * D_DIM + i) = lo;
    }
}

// ---------------- bf16-split tensor-core GEMM (NT) --------------------------
// C[M,N] = (Ah+Al)[M,K] @ (Bh+Bl)[N,K]^T ; 3 MMA terms per k16.
// Inputs are pre-split bf16 arrays. Round-2 loop structure (proven).
enum { EPI_BIAS = 0, EPI_PHI = 1, EPI_GELU = 2, EPI_RES = 3 };

__device__ __forceinline__ void mma_bf16(float* c, const unsigned* a, const unsigned* b) {
    asm volatile(
        "mma.sync.aligned.m16n8k16.row.col.f32.bf16.bf16.f32 "
        "{%0,%1,%2,%3}, {%4,%5,%6,%7}, {%8,%9}, {%0,%1,%2,%3};\n"
        : "+f"(c[0]), "+f"(c[1]), "+f"(c[2]), "+f"(c[3])
        : "r"(a[0]), "r"(a[1]), "r"(a[2]), "r"(a[3]), "r"(b[0]), "r"(b[1]));
}

#define LDSW 40

template <int EPI>
__global__ __launch_bounds__(256, 1)
void gemm_bf(const __nv_bfloat16* __restrict__ Ahg, const __nv_bfloat16* __restrict__ Alg,
             const __nv_bfloat16* __restrict__ Bhg, const __nv_bfloat16* __restrict__ Blg,
             const float* __restrict__ bias, const float* __restrict__ res,
             float* __restrict__ Cf,
             __nv_bfloat16* __restrict__ Chi, __nv_bfloat16* __restrict__ Clo,
             int M, int N, int K) {
    __shared__ __align__(16) __nv_bfloat16 Ah[128 * LDSW];
    __shared__ __align__(16) __nv_bfloat16 Al[128 * LDSW];
    __shared__ __align__(16) __nv_bfloat16 Bh[128 * LDSW];
    __shared__ __align__(16) __nv_bfloat16 Bl[128 * LDSW];

    const int tid  = threadIdx.x;
    const int bm   = blockIdx.y * 128, bn = blockIdx.x * 128;
    const int lane = tid & 31, warp = tid >> 5;
    const int wm   = (warp & 3) * 32;
    const int wn   = (warp >> 2) * 64;
    const int g    = lane >> 2;
    const int tg   = (lane & 3) * 2;

    const int lrow = tid >> 1;            // 0..127
    const int lc   = (tid & 1) * 16;      // 0 or 16

    float acc[2][8][4];
#pragma unroll
    for (int i = 0; i < 2; i++)
#pragma unroll
        for (int j = 0; j < 8; j++)
#pragma unroll
            for (int e = 0; e < 4; e++) acc[i][j][e] = 0.f;

    const size_t offA = (size_t)(bm + lrow) * K + lc;
    const size_t offB = (size_t)(bn + lrow) * K + lc;

    uint4 rAh[2], rAl[2], rBh[2], rBl[2];
#pragma unroll
    for (int j = 0; j < 2; j++) {
        rAh[j] = *(const uint4*)(Ahg + offA + 8 * j);
        rAl[j] = *(const uint4*)(Alg + offA + 8 * j);
        rBh[j] = *(const uint4*)(Bhg + offB + 8 * j);
        rBl[j] = *(const uint4*)(Blg + offB + 8 * j);
    }

    const int nb = K / 32;
    for (int t = 0; t < nb; t++) {
        __syncthreads();
#pragma unroll
        for (int j = 0; j < 2; j++) {
            *(uint4*)&Ah[lrow * LDSW + lc + 8 * j] = rAh[j];
            *(uint4*)&Al[lrow * LDSW + lc + 8 * j] = rAl[j];
            *(uint4*)&Bh[lrow * LDSW + lc + 8 * j] = rBh[j];
            *(uint4*)&Bl[lrow * LDSW + lc + 8 * j] = rBl[j];
        }
        __syncthreads();
        if (t + 1 < nb) {
            int kt = (t + 1) * 32;
#pragma unroll
            for (int j = 0; j < 2; j++) {
                rAh[j] = *(const uint4*)(Ahg + offA + kt + 8 * j);
                rAl[j] = *(const uint4*)(Alg + offA + kt + 8 * j);
                rBh[j] = *(const uint4*)(Bhg + offB + kt + 8 * j);
                rBl[j] = *(const uint4*)(Blg + offB + kt + 8 * j);
            }
        }
#pragma unroll
        for (int kk = 0; kk < 32; kk += 16) {
            unsigned ah[2][4], al[2][4], bh[8][2], bl[8][2];
#pragma unroll
            for (int mi = 0; mi < 2; mi++) {
                int r0 = wm + mi * 16 + g;
                ah[mi][0] = *(const unsigned*)&Ah[(r0    ) * LDSW + kk + tg    ];
                ah[mi][1] = *(const unsigned*)&Ah[(r0 + 8) * LDSW + kk + tg    ];
                ah[mi][2] = *(const unsigned*)&Ah[(r0    ) * LDSW + kk + tg + 8];
                ah[mi][3] = *(const unsigned*)&Ah[(r0 + 8) * LDSW + kk + tg + 8];
                al[mi][0] = *(const unsigned*)&Al[(r0    ) * LDSW + kk + tg    ];
                al[mi][1] = *(const unsigned*)&Al[(r0 + 8) * LDSW + kk + tg    ];
                al[mi][2] = *(const unsigned*)&Al[(r0    ) * LDSW + kk + tg + 8];
                al[mi][3] = *(const unsigned*)&Al[(r0 + 8) * LDSW + kk + tg + 8];
            }
#pragma unroll
            for (int ni = 0; ni < 8; ni++) {
                int c0 = wn + ni * 8 + g;
                bh[ni][0] = *(const unsigned*)&Bh[c0 * LDSW + kk + tg    ];
                bh[ni][1] = *(const unsigned*)&Bh[c0 * LDSW + kk + tg + 8];
                bl[ni][0] = *(const unsigned*)&Bl[c0 * LDSW + kk + tg    ];
                bl[ni][1] = *(const unsigned*)&Bl[c0 * LDSW + kk + tg + 8];
            }
#pragma unroll
            for (int mi = 0; mi < 2; mi++)
#pragma unroll
                for (int ni = 0; ni < 8; ni++) {
                    mma_bf16(acc[mi][ni], ah[mi], bh[ni]);
                    mma_bf16(acc[mi][ni], ah[mi], bl[ni]);
                    mma_bf16(acc[mi][ni], al[mi], bh[ni]);
                }
        }
    }

    // epilogue
#pragma unroll
    for (int mi = 0; mi < 2; mi++)
#pragma unroll
        for (int ni = 0; ni < 8; ni++) {
            int r0 = bm + wm + mi * 16 + g;
            int c0 = bn + wn + ni * 8 + tg;
#pragma unroll
            for (int half = 0; half < 2; half++) {
                int r = r0 + half * 8;
                float v0 = acc[mi][ni][half * 2 + 0] + bias[c0];
                float v1 = acc[mi][ni][half * 2 + 1] + bias[c0 + 1];
                if (EPI == EPI_PHI) {
                    v0 = (v0 > 0.f) ? (v0 + 1.f) : expf(v0);
                    v1 = (v1 > 0.f) ? (v1 + 1.f) : expf(v1);
                }
                if (EPI == EPI_GELU) {
                    v0 = 0.5f * v0 * (1.f + erff(v0 * 0.70710678118654752f));
                    v1 = 0.5f * v1 * (1.f + erff(v1 * 0.70710678118654752f));
                    __nv_bfloat16 h0, l0, h1, l1;
                    split2(v0, h0, l0);
                    split2(v1, h1, l1);
                    __nv_bfloat162 hh; hh.x = h0; hh.y = h1;
                    __nv_bfloat162 ll; ll.x = l0; ll.y = l1;
                    *(__nv_bfloat162*)(Chi + (size_t)r * N + c0) = hh;
                    *(__nv_bfloat162*)(Clo + (size_t)r * N + c0) = ll;
                    continue;
                }
                if (EPI == EPI_RES) {
                    float2 rv = *(const float2*)(res + (size_t)r * N + c0);
                    v0 += rv.x; v1 += rv.y;
                }
                float2 o = make_float2(v0, v1);
                *(float2*)(Cf + (size_t)r * N + c0) = o;
            }
        }
}

// ---------------- Pass A: per-chunk KV sums -------------------------------
__global__ void chunk_kv_kernel() {
    __shared__ float ks[CCH * (HDIM + 1)];
    __shared__ float vs[CCH * (HDIM + 1)];
    int blk = blockIdx.x, h = blk / NCH, c = blk % NCH, tid = threadIdx.x;
    int s0 = c * CCH;
    for (int i = tid; i < CCH * HDIM; i += 256) {
        int r = i >> 6, d = i & 63;
        ks[r * (HDIM + 1) + d] = g_k[(size_t)(s0 + r) * D_DIM + h * HDIM + d];
        vs[r * (HDIM + 1) + d] = g_v[(size_t)(s0 + r) * D_DIM + h * HDIM + d];
    }
    __syncthreads();
    int d = tid >> 2, e0 = (tid & 3) * 16;
    float acc[16] = {};
    for (int s = 0; s < CCH; s++) {
        float kd = ks[s * (HDIM + 1) + d];
#pragma unroll
        for (int j = 0; j < 16; j++)
            acc[j] += kd * vs[s * (HDIM + 1) + e0 + j];
    }
    float* outp = g_kv + ((size_t)(h * NCH + c) * HDIM + d) * HDIM + e0;
#pragma unroll
    for (int j = 0; j < 16; j++) outp[j] = acc[j];
    if (tid < HDIM) {
        float z = 0.f;
        for (int s = 0; s < CCH; s++) z += ks[s * (HDIM + 1) + tid];
        g_zc[(h * NCH + c) * HDIM + tid] = z;
    }
}

// ---------------- Pass B: exclusive prefix over chunks (float4) -----------
__global__ void prefix_kernel() {
    int idx = blockIdx.x * 256 + threadIdx.x;     // 16384 threads
    int h = idx >> 10, de4 = idx & 1023;
    const float4* in  = (const float4*)g_kv;
    float4*       out = (float4*)g_kvp;
    float4 run = make_float4(0.f, 0.f, 0.f, 0.f);
#pragma unroll 4
    for (int c = 0; c < NCH; c++) {
        size_t off = (size_t)(h * NCH + c) * 1024 + de4;
        float4 v = in[off];
        out[off] = run;
        run.x += v.x; run.y += v.y; run.z += v.z; run.w += v.w;
    }
    if (idx < H_NUM * HDIM) {
        int ho = idx / HDIM, dd = idx % HDIM;
        float rz = 0.f;
        for (int c = 0; c < NCH; c++) {
            int off = (ho * NCH + c) * HDIM + dd;
            float v = g_zc[off];
            g_zp[off] = rz;
            rz += v;
        }
    }
}

// ---------------- Pass C: per-chunk attention output (split bf16 out) -----
__global__ void chunk_attn_kernel() {
    extern __shared__ float sm[];
    float* qs = sm;
    float* kv = qs + CCH * (HDIM + 1);
    float* Ss = kv + CCH * (HDIM + 1);
    float* kp = Ss + CCH * (CCH + 1);
    float* zp = kp + HDIM * (HDIM + 1);
    float* dn = zp + HDIM;

    int blk = blockIdx.x, h = blk / NCH, c = blk % NCH, tid = threadIdx.x;
    int s0 = c * CCH;

    for (int i = tid; i < CCH * HDIM; i += 256) {
        int r = i >> 6, d = i & 63;
        qs[r * (HDIM + 1) + d] = g_q[(size_t)(s0 + r) * D_DIM + h * HDIM + d];
        kv[r * (HDIM + 1) + d] = g_k[(size_t)(s0 + r) * D_DIM + h * HDIM + d];
        kp[r * (HDIM + 1) + d] = g_kvp[((size_t)(h * NCH + c) * HDIM + r) * HDIM + d];
    }
    if (tid < HDIM) zp[tid] = g_zp[(h * NCH + c) * HDIM + tid];
    __syncthreads();

    {
        int t = tid >> 2, i0 = (tid & 3) * 16;
        for (int j = 0; j < 16; j++) {
            int i = i0 + j;
            float sc = 0.f;
            if (i <= t) {
#pragma unroll
                for (int d = 0; d < HDIM; d++)
                    sc += qs[t * (HDIM + 1) + d] * kv[i * (HDIM + 1) + d];
            }
            Ss[t * (CCH + 1) + i] = sc;
        }
    }
    __syncthreads();

    if (tid < CCH) {
        float dd = 1e-6f;
        for (int d = 0; d < HDIM; d++)
            dd += qs[tid * (HDIM + 1) + d] * zp[d];
        for (int i = 0; i < CCH; i++)
            dd += Ss[tid * (CCH + 1) + i];
        dn[tid] = dd;
    }
    for (int i = tid; i < CCH * HDIM; i += 256) {
        int r = i >> 6, d = i & 63;
        kv[r * (HDIM + 1) + d] = g_v[(size_t)(s0 + r) * D_DIM + h * HDIM + d];
    }
    __syncthreads();

    int t = tid >> 2, e0 = (tid & 3) * 16;
    float o[16] = {};
    for (int d = 0; d < HDIM; d++) {
        float qd = qs[t * (HDIM + 1) + d];
#pragma unroll
        for (int j = 0; j < 16; j++)
            o[j] += qd * kp[d * (HDIM + 1) + e0 + j];
    }
    for (int i = 0; i < CCH; i++) {
        float sv = Ss[t * (CCH + 1) + i];
#pragma unroll
        for (int j = 0; j < 16; j++)
            o[j] += sv * kv[i * (HDIM + 1) + e0 + j];
    }
    float inv = 1.f / dn[t];
    size_t base = (size_t)(s0 + t) * D_DIM + h * HDIM + e0;
#pragma unroll
    for (int j = 0; j < 16; j += 4) {
        float4 y;
        y.x = o[j + 0] * inv; y.y = o[j + 1] * inv;
        y.z = o[j + 2] * inv; y.w = o[j + 3] * inv;
        uint2 lo, hi = cvt_hi_lo(y, lo);
        *(uint2*)(g_at_hi + base + j) = hi;
        *(uint2*)(g_at_lo + base + j) = lo;
    }
}

// ---------------- launch ---------------------------------------------------
extern "C" void kernel_launch(void* const* d_in, const int* in_sizes, int n_in,
                              void* d_out, int out_size) {
    const float* x   = (const float*)d_in[0];
    const float* Wq  = (const float*)d_in[1];  const float* bq  = (const float*)d_in[2];
    const float* Wk  = (const float*)d_in[3];  const float* bk  = (const float*)d_in[4];
    const float* Wv  = (const float*)d_in[5];  const float* bv  = (const float*)d_in[6];
    const float* Wo  = (const float*)d_in[7];  const float* bo  = (const float*)d_in[8];
    const float* W1  = (const float*)d_in[9];  const float* b1  = (const float*)d_in[10];
    const float* W2  = (const float*)d_in[11]; const float* b2  = (const float*)d_in[12];
    const float* g1  = (const float*)d_in[13]; const float* be1 = (const float*)d_in[14];
    const float* g2  = (const float*)d_in[15]; const float* be2 = (const float*)d_in[16];
    float* out = (float*)d_out;

    float *q, *k, *v, *x2;
    cudaGetSymbolAddress((void**)&q,  g_q);
    cudaGetSymbolAddress((void**)&k,  g_k);
    cudaGetSymbolAddress((void**)&v,  g_v);
    cudaGetSymbolAddress((void**)&x2, g_x2);
    __nv_bfloat16 *hhi, *hlo, *h2hi, *h2lo, *athi, *atlo, *ffhi, *fflo;
    __nv_bfloat16 *wqh, *wql, *wkh, *wkl, *wvh, *wvl, *woh, *wol, *w1h, *w1l, *w2h, *w2l;
    cudaGetSymbolAddress((void**)&hhi,  g_h_hi);  cudaGetSymbolAddress((void**)&hlo,  g_h_lo);
    cudaGetSymbolAddress((void**)&h2hi, g_h2_hi); cudaGetSymbolAddress((void**)&h2lo, g_h2_lo);
    cudaGetSymbolAddress((void**)&athi, g_at_hi); cudaGetSymbolAddress((void**)&atlo, g_at_lo);
    cudaGetSymbolAddress((void**)&ffhi, g_ff_hi); cudaGetSymbolAddress((void**)&fflo, g_ff_lo);
    cudaGetSymbolAddress((void**)&wqh, g_wq_hi);  cudaGetSymbolAddress((void**)&wql, g_wq_lo);
    cudaGetSymbolAddress((void**)&wkh, g_wk_hi);  cudaGetSymbolAddress((void**)&wkl, g_wk_lo);
    cudaGetSymbolAddress((void**)&wvh, g_wv_hi);  cudaGetSymbolAddress((void**)&wvl, g_wv_lo);
    cudaGetSymbolAddress((void**)&woh, g_wo_hi);  cudaGetSymbolAddress((void**)&wol, g_wo_lo);
    cudaGetSymbolAddress((void**)&w1h, g_w1_hi);  cudaGetSymbolAddress((void**)&w1l, g_w1_lo);
    cudaGetSymbolAddress((void**)&w2h, g_w2_hi);  cudaGetSymbolAddress((void**)&w2l, g_w2_lo);

    const int smem_attn = (2 * CCH * (HDIM + 1) + CCH * (CCH + 1) +
                           HDIM * (HDIM + 1) + HDIM + CCH) * (int)sizeof(float);
    cudaFuncSetAttribute(chunk_attn_kernel,
                         cudaFuncAttributeMaxDynamicSharedMemorySize, smem_attn);

    const int nDD = D_DIM * D_DIM, nFD = FF_DIM * D_DIM;

    // 1. weight splits
    cvt_split<<<nDD / 1024, 256>>>(Wq, wqh, wql, nDD);
    cvt_split<<<nDD / 1024, 256>>>(Wk, wkh, wkl, nDD);
    cvt_split<<<nDD / 1024, 256>>>(Wv, wvh, wvl, nDD);
    cvt_split<<<nDD / 1024, 256>>>(Wo, woh, wol, nDD);
    cvt_split<<<nFD / 1024, 256>>>(W1, w1h, w1l, nFD);
    cvt_split<<<nFD / 1024, 256>>>(W2, w2h, w2l, nFD);

    dim3 gD(D_DIM / 128, S_LEN / 128);
    dim3 gF(FF_DIM / 128, S_LEN / 128);

    // 2. LN1 (split out)
    ln_split<<<S_LEN, 256>>>(x, g1, be1, hhi, hlo);

    // 3. QKV
    gemm_bf<EPI_PHI> <<<gD, 256>>>(hhi, hlo, wqh, wql, bq, nullptr, q, nullptr, nullptr, S_LEN, D_DIM, D_DIM);
    gemm_bf<EPI_PHI> <<<gD, 256>>>(hhi, hlo, wkh, wkl, bk, nullptr, k, nullptr, nullptr, S_LEN, D_DIM, D_DIM);
    gemm_bf<EPI_BIAS><<<gD, 256>>>(hhi, hlo, wvh, wvl, bv, nullptr, v, nullptr, nullptr, S_LEN, D_DIM, D_DIM);

    // 4. attention
    chunk_kv_kernel  <<<H_NUM * NCH, 256>>>();
    prefix_kernel    <<<H_NUM * HDIM * HDIM / 4 / 256, 256>>>();
    chunk_attn_kernel<<<H_NUM * NCH, 256, smem_attn>>>();

    // 5. O-proj (+residual)
    gemm_bf<EPI_RES> <<<gD, 256>>>(athi, atlo, woh, wol, bo, x, x2, nullptr, nullptr, S_LEN, D_DIM, D_DIM);

    // 6. LN2 (split out)
    ln_split<<<S_LEN, 256>>>(x2, g2, be2, h2hi, h2lo);

    // 7. FFN1 (GELU, split out)
    gemm_bf<EPI_GELU><<<gF, 256>>>(h2hi, h2lo, w1h, w1l, b1, nullptr, nullptr, ffhi, fflo, S_LEN, FF_DIM, D_DIM);

    // 8. FFN2 (+residual) -> out
    gemm_bf<EPI_RES> <<<gD, 256>>>(ffhi, fflo, w2h, w2l, b2, x2, out, nullptr, nullptr, S_LEN, D_DIM, FF_DIM);
}

// round 6
// speedup vs baseline: 1.1027x; 1.1027x over previous
#include <cuda_runtime.h>
#include <cuda_bf16.h>
#include <math.h>
#include <stdint.h>

// Problem constants
#define S_LEN 2048
#define D_DIM 1024
#define H_NUM 16
#define HDIM  64
#define FF_DIM 4096
#define CCH   64
#define NCH   (S_LEN/CCH)

// ---------------- scratch (static device globals; no allocation) ----------
__device__ float g_h   [S_LEN*D_DIM];
__device__ float g_q   [S_LEN*D_DIM];
__device__ float g_k   [S_LEN*D_DIM];
__device__ float g_v   [S_LEN*D_DIM];
__device__ float g_attn[S_LEN*D_DIM];
__device__ float g_x2  [S_LEN*D_DIM];
__device__ float g_h2  [S_LEN*D_DIM];
__device__ float g_ff  [S_LEN*FF_DIM];
__device__ float g_kv  [H_NUM*NCH*HDIM*HDIM];
__device__ float g_kvp [H_NUM*NCH*HDIM*HDIM];
__device__ float g_zc  [H_NUM*NCH*HDIM];
__device__ float g_zp  [H_NUM*NCH*HDIM];

// ---------------- LayerNorm -------------------------------------------------
__global__ void ln_kernel(const float* __restrict__ x,
                          const float* __restrict__ g,
                          const float* __restrict__ b,
                          float* __restrict__ out) {
    int row = blockIdx.x;
    const float* xr = x + (size_t)row * D_DIM;
    float s = 0.f, s2 = 0.f;
    for (int i = threadIdx.x; i < D_DIM; i += 256) {
        float v = xr[i];
        s += v; s2 += v * v;
    }
    __shared__ float sh[64];
    for (int off = 16; off > 0; off >>= 1) {
        s  += __shfl_down_sync(0xffffffffu, s,  off);
        s2 += __shfl_down_sync(0xffffffffu, s2, off);
    }
    int w = threadIdx.x >> 5, l = threadIdx.x & 31;
    if (l == 0) { sh[w] = s; sh[w + 32] = s2; }
    __syncthreads();
    if (threadIdx.x == 0) {
        float ts = 0.f, ts2 = 0.f;
        for (int i = 0; i < 8; i++) { ts += sh[i]; ts2 += sh[i + 32]; }
        float mu = ts / D_DIM;
        sh[0] = mu;
        sh[1] = rsqrtf(ts2 / D_DIM - mu * mu + 1e-5f);
    }
    __syncthreads();
    float mu = sh[0], rstd = sh[1];
    for (int i = threadIdx.x; i < D_DIM; i += 256)
        out[(size_t)row * D_DIM + i] = (xr[i] - mu) * rstd * g[i] + b[i];
}

// ---------------- bf16-split tensor-core GEMM (NT) -------------------------
// C[M,N] = A[M,K] @ B[N,K]^T + epilogue, fp32 in/out.
// Each fp32 = hi_bf16 + lo_bf16; per k16: mma(hi,hi)+mma(hi,lo)+mma(lo,hi).
enum { EPI_BIAS = 0, EPI_PHI = 1, EPI_GELU = 2, EPI_RES = 3 };

__device__ __forceinline__ void mma_bf16(float* c, const unsigned* a, const unsigned* b) {
    asm volatile(
        "mma.sync.aligned.m16n8k16.row.col.f32.bf16.bf16.f32 "
        "{%0,%1,%2,%3}, {%4,%5,%6,%7}, {%8,%9}, {%0,%1,%2,%3};\n"
        : "+f"(c[0]), "+f"(c[1]), "+f"(c[2]), "+f"(c[3])
        : "r"(a[0]), "r"(a[1]), "r"(a[2]), "r"(a[3]), "r"(b[0]), "r"(b[1]));
}

__device__ __forceinline__ void ldsm_x4(unsigned* r, uint32_t addr) {
    asm volatile(
        "ldmatrix.sync.aligned.m8n8.x4.shared.b16 {%0,%1,%2,%3}, [%4];"
        : "=r"(r[0]), "=r"(r[1]), "=r"(r[2]), "=r"(r[3]) : "r"(addr));
}

template <int EPI>
__global__ __launch_bounds__(256, 1)
void gemm_mma(const float* __restrict__ A, const float* __restrict__ B,
              const float* __restrict__ bias, const float* __restrict__ res,
              float* __restrict__ Cmat, int M, int N, int K) {
    const int BM = 128, BN = 128, BK = 32, LDS = 40;   // stride 40 -> conflict-free
    __shared__ __align__(16) __nv_bfloat16 Ah[BM * LDS];
    __shared__ __align__(16) __nv_bfloat16 Al[BM * LDS];
    __shared__ __align__(16) __nv_bfloat16 Bh[BN * LDS];
    __shared__ __align__(16) __nv_bfloat16 Bl[BN * LDS];

    const int tid  = threadIdx.x;
    const int bm   = blockIdx.y * BM, bn = blockIdx.x * BN;
    const int lane = tid & 31, warp = tid >> 5;
    const int wm   = (warp & 3) * 32;     // 4 warps along M
    const int wn   = (warp >> 2) * 64;    // 2 warps along N
    const int g    = lane >> 2;           // 0..7
    const int tg   = (lane & 3) * 2;      // 0,2,4,6

    const int lrow = tid >> 3;            // 0..31 (loader row)
    const int lcol = (tid & 7) * 4;       // 0..28 (float4 col)

    float acc[2][8][4];
#pragma unroll
    for (int i = 0; i < 2; i++)
#pragma unroll
        for (int j = 0; j < 8; j++)
#pragma unroll
            for (int e = 0; e < 4; e++) acc[i][j][e] = 0.f;

    const float* Ap = A + (size_t)(bm + lrow) * K + lcol;
    const float* Bp = B + (size_t)(bn + lrow) * K + lcol;

    float4 ar[4], br[4];
#pragma unroll
    for (int i = 0; i < 4; i++) {
        ar[i] = *(const float4*)(Ap + (size_t)(32 * i) * K);
        br[i] = *(const float4*)(Bp + (size_t)(32 * i) * K);
    }

    // ldmatrix per-lane base addresses (bytes)
    const uint32_t aHiB = (uint32_t)__cvta_generic_to_shared(Ah);
    const uint32_t aLoB = (uint32_t)__cvta_generic_to_shared(Al);
    const uint32_t bHiB = (uint32_t)__cvta_generic_to_shared(Bh);
    const uint32_t bLoB = (uint32_t)__cvta_generic_to_shared(Bl);
    const uint32_t lrow16 = lane & 15, lhalf = (lane >> 4) * 8;
    const uint32_t aoff = (uint32_t)(((wm + lrow16) * LDS + lhalf) * 2);
    const uint32_t boff = (uint32_t)(((wn + lrow16) * LDS + lhalf) * 2);

    for (int kt = 0; kt < K; kt += BK) {
        __syncthreads();
#pragma unroll
        for (int i = 0; i < 4; i++) {
            int r = lrow + 32 * i;
            float av[4] = {ar[i].x, ar[i].y, ar[i].z, ar[i].w};
            float bv[4] = {br[i].x, br[i].y, br[i].z, br[i].w};
#pragma unroll
            for (int j = 0; j < 4; j++) {
                __nv_bfloat16 h = __float2bfloat16(av[j]);
                Ah[r * LDS + lcol + j] = h;
                Al[r * LDS + lcol + j] = __float2bfloat16(av[j] - __bfloat162float(h));
                __nv_bfloat16 h2 = __float2bfloat16(bv[j]);
                Bh[r * LDS + lcol + j] = h2;
                Bl[r * LDS + lcol + j] = __float2bfloat16(bv[j] - __bfloat162float(h2));
            }
        }
        __syncthreads();
        if (kt + BK < K) {
#pragma unroll
            for (int i = 0; i < 4; i++) {
                ar[i] = *(const float4*)(Ap + (kt + BK) + (size_t)(32 * i) * K);
                br[i] = *(const float4*)(Bp + (kt + BK) + (size_t)(32 * i) * K);
            }
        }
#pragma unroll
        for (int kk = 0; kk < BK; kk += 16) {
            unsigned ah[2][4], al[2][4], bh[8][2], bl[8][2];
            const uint32_t kkb = (uint32_t)(kk * 2);
#pragma unroll
            for (int mi = 0; mi < 2; mi++) {
                uint32_t off = aoff + (uint32_t)(mi * 16 * LDS * 2) + kkb;
                ldsm_x4(ah[mi], aHiB + off);
                ldsm_x4(al[mi], aLoB + off);
            }
#pragma unroll
            for (int np = 0; np < 4; np++) {          // ni pair {2np, 2np+1}
                unsigned t4[4];
                uint32_t off = boff + (uint32_t)(np * 16 * LDS * 2) + kkb;
                ldsm_x4(t4, bHiB + off);
                bh[2 * np    ][0] = t4[0]; bh[2 * np + 1][0] = t4[1];
                bh[2 * np    ][1] = t4[2]; bh[2 * np + 1][1] = t4[3];
                ldsm_x4(t4, bLoB + off);
                bl[2 * np    ][0] = t4[0]; bl[2 * np + 1][0] = t4[1];
                bl[2 * np    ][1] = t4[2]; bl[2 * np + 1][1] = t4[3];
            }
#pragma unroll
            for (int mi = 0; mi < 2; mi++)
#pragma unroll
                for (int ni = 0; ni < 8; ni++) {
                    mma_bf16(acc[mi][ni], ah[mi], bh[ni]);
                    mma_bf16(acc[mi][ni], ah[mi], bl[ni]);
                    mma_bf16(acc[mi][ni], al[mi], bh[ni]);
                }
        }
    }

    // epilogue: thread owns (r0,c0),(r0,c0+1),(r0+8,c0),(r0+8,c0+1) per tile
#pragma unroll
    for (int mi = 0; mi < 2; mi++)
#pragma unroll
        for (int ni = 0; ni < 8; ni++) {
            int r0 = bm + wm + mi * 16 + g;
            int c0 = bn + wn + ni * 8 + tg;
#pragma unroll
            for (int half = 0; half < 2; half++) {
                int r = r0 + half * 8;
                float v0 = acc[mi][ni][half * 2 + 0] + bias[c0];
                float v1 = acc[mi][ni][half * 2 + 1] + bias[c0 + 1];
                if (EPI == EPI_PHI) {
                    v0 = (v0 > 0.f) ? (v0 + 1.f) : expf(v0);
                    v1 = (v1 > 0.f) ? (v1 + 1.f) : expf(v1);
                }
                if (EPI == EPI_GELU) {
                    v0 = 0.5f * v0 * (1.f + erff(v0 * 0.70710678118654752f));
                    v1 = 0.5f * v1 * (1.f + erff(v1 * 0.70710678118654752f));
                }
                if (EPI == EPI_RES) {
                    float2 rv = *(const float2*)(res + (size_t)r * N + c0);
                    v0 += rv.x; v1 += rv.y;
                }
                float2 o = make_float2(v0, v1);
                *(float2*)(Cmat + (size_t)r * N + c0) = o;
            }
        }
}

// ---------------- Pass A: per-chunk KV sums -------------------------------
__global__ void chunk_kv_kernel() {
    __shared__ float ks[CCH * (HDIM + 1)];
    __shared__ float vs[CCH * (HDIM + 1)];
    int blk = blockIdx.x, h = blk / NCH, c = blk % NCH, tid = threadIdx.x;
    int s0 = c * CCH;
    for (int i = tid; i < CCH * HDIM; i += 256) {
        int r = i >> 6, d = i & 63;
        ks[r * (HDIM + 1) + d] = g_k[(size_t)(s0 + r) * D_DIM + h * HDIM + d];
        vs[r * (HDIM + 1) + d] = g_v[(size_t)(s0 + r) * D_DIM + h * HDIM + d];
    }
    __syncthreads();
    int d = tid >> 2, e0 = (tid & 3) * 16;
    float acc[16] = {};
    for (int s = 0; s < CCH; s++) {
        float kd = ks[s * (HDIM + 1) + d];
#pragma unroll
        for (int j = 0; j < 16; j++)
            acc[j] += kd * vs[s * (HDIM + 1) + e0 + j];
    }
    float* outp = g_kv + ((size_t)(h * NCH + c) * HDIM + d) * HDIM + e0;
#pragma unroll
    for (int j = 0; j < 16; j++) outp[j] = acc[j];
    if (tid < HDIM) {
        float z = 0.f;
        for (int s = 0; s < CCH; s++) z += ks[s * (HDIM + 1) + tid];
        g_zc[(h * NCH + c) * HDIM + tid] = z;
    }
}

// ---------------- Pass B: exclusive prefix over chunks (float4) -----------
__global__ void prefix_kernel() {
    int idx = blockIdx.x * 256 + threadIdx.x;     // 16384 threads
    int h = idx >> 10, de4 = idx & 1023;
    const float4* in  = (const float4*)g_kv;
    float4*       out = (float4*)g_kvp;
    float4 run = make_float4(0.f, 0.f, 0.f, 0.f);
#pragma unroll 4
    for (int c = 0; c < NCH; c++) {
        size_t off = (size_t)(h * NCH + c) * 1024 + de4;
        float4 v = in[off];
        out[off] = run;
        run.x += v.x; run.y += v.y; run.z += v.z; run.w += v.w;
    }
    if (idx < H_NUM * HDIM) {
        int ho = idx / HDIM, dd = idx % HDIM;
        float rz = 0.f;
        for (int c = 0; c < NCH; c++) {
            int off = (ho * NCH + c) * HDIM + dd;
            float v = g_zc[off];
            g_zp[off] = rz;
            rz += v;
        }
    }
}

// ---------------- Pass C: per-chunk attention output ----------------------
__global__ void chunk_attn_kernel() {
    extern __shared__ float sm[];
    float* qs = sm;
    float* kv = qs + CCH * (HDIM + 1);
    float* Ss = kv + CCH * (HDIM + 1);
    float* kp = Ss + CCH * (CCH + 1);
    float* zp = kp + HDIM * (HDIM + 1);
    float* dn = zp + HDIM;

    int blk = blockIdx.x, h = blk / NCH, c = blk % NCH, tid = threadIdx.x;
    int s0 = c * CCH;

    for (int i = tid; i < CCH * HDIM; i += 256) {
        int r = i >> 6, d = i & 63;
        qs[r * (HDIM + 1) + d] = g_q[(size_t)(s0 + r) * D_DIM + h * HDIM + d];
        kv[r * (HDIM + 1) + d] = g_k[(size_t)(s0 + r) * D_DIM + h * HDIM + d];
        kp[r * (HDIM + 1) + d] = g_kvp[((size_t)(h * NCH + c) * HDIM + r) * HDIM + d];
    }
    if (tid < HDIM) zp[tid] = g_zp[(h * NCH + c) * HDIM + tid];
    __syncthreads();

    {
        int t = tid >> 2, i0 = (tid & 3) * 16;
        for (int j = 0; j < 16; j++) {
            int i = i0 + j;
            float sc = 0.f;
            if (i <= t) {
#pragma unroll
                for (int d = 0; d < HDIM; d++)
                    sc += qs[t * (HDIM + 1) + d] * kv[i * (HDIM + 1) + d];
            }
            Ss[t * (CCH + 1) + i] = sc;
        }
    }
    __syncthreads();

    if (tid < CCH) {
        float dd = 1e-6f;
        for (int d = 0; d < HDIM; d++)
            dd += qs[tid * (HDIM + 1) + d] * zp[d];
        for (int i = 0; i < CCH; i++)
            dd += Ss[tid * (CCH + 1) + i];
        dn[tid] = dd;
    }
    for (int i = tid; i < CCH * HDIM; i += 256) {
        int r = i >> 6, d = i & 63;
        kv[r * (HDIM + 1) + d] = g_v[(size_t)(s0 + r) * D_DIM + h * HDIM + d];
    }
    __syncthreads();

    int t = tid >> 2, e0 = (tid & 3) * 16;
    float o[16] = {};
    for (int d = 0; d < HDIM; d++) {
        float qd = qs[t * (HDIM + 1) + d];
#pragma unroll
        for (int j = 0; j < 16; j++)
            o[j] += qd * kp[d * (HDIM + 1) + e0 + j];
    }
    for (int i = 0; i < CCH; i++) {
        float sv = Ss[t * (CCH + 1) + i];
#pragma unroll
        for (int j = 0; j < 16; j++)
            o[j] += sv * kv[i * (HDIM + 1) + e0 + j];
    }
    float inv = 1.f / dn[t];
    float* op = g_attn + (size_t)(s0 + t) * D_DIM + h * HDIM + e0;
#pragma unroll
    for (int j = 0; j < 16; j++) op[j] = o[j] * inv;
}

// ---------------- launch ---------------------------------------------------
extern "C" void kernel_launch(void* const* d_in, const int* in_sizes, int n_in,
                              void* d_out, int out_size) {
    const float* x   = (const float*)d_in[0];
    const float* Wq  = (const float*)d_in[1];  const float* bq  = (const float*)d_in[2];
    const float* Wk  = (const float*)d_in[3];  const float* bk  = (const float*)d_in[4];
    const float* Wv  = (const float*)d_in[5];  const float* bv  = (const float*)d_in[6];
    const float* Wo  = (const float*)d_in[7];  const float* bo  = (const float*)d_in[8];
    const float* W1  = (const float*)d_in[9];  const float* b1  = (const float*)d_in[10];
    const float* W2  = (const float*)d_in[11]; const float* b2  = (const float*)d_in[12];
    const float* g1  = (const float*)d_in[13]; const float* be1 = (const float*)d_in[14];
    const float* g2  = (const float*)d_in[15]; const float* be2 = (const float*)d_in[16];
    float* out = (float*)d_out;

    float *h, *q, *k, *v, *attn, *x2, *h2, *ff;
    cudaGetSymbolAddress((void**)&h,    g_h);
    cudaGetSymbolAddress((void**)&q,    g_q);
    cudaGetSymbolAddress((void**)&k,    g_k);
    cudaGetSymbolAddress((void**)&v,    g_v);
    cudaGetSymbolAddress((void**)&attn, g_attn);
    cudaGetSymbolAddress((void**)&x2,   g_x2);
    cudaGetSymbolAddress((void**)&h2,   g_h2);
    cudaGetSymbolAddress((void**)&ff,   g_ff);

    const int smem_attn = (2 * CCH * (HDIM + 1) + CCH * (CCH + 1) +
                           HDIM * (HDIM + 1) + HDIM + CCH) * (int)sizeof(float);
    cudaFuncSetAttribute(chunk_attn_kernel,
                         cudaFuncAttributeMaxDynamicSharedMemorySize, smem_attn);

    dim3 gD(D_DIM / 128, S_LEN / 128);      // 8 x 16
    dim3 gF(FF_DIM / 128, S_LEN / 128);     // 32 x 16

    ln_kernel<<<S_LEN, 256>>>(x, g1, be1, h);
    gemm_mma<EPI_PHI> <<<gD, 256>>>(h, Wq, bq, nullptr, q, S_LEN, D_DIM, D_DIM);
    gemm_mma<EPI_PHI> <<<gD, 256>>>(h, Wk, bk, nullptr, k, S_LEN, D_DIM, D_DIM);
    gemm_mma<EPI_BIAS><<<gD, 256>>>(h, Wv, bv, nullptr, v, S_LEN, D_DIM, D_DIM);
    chunk_kv_kernel  <<<H_NUM * NCH, 256>>>();
    prefix_kernel    <<<H_NUM * HDIM * HDIM / 4 / 256, 256>>>();
    chunk_attn_kernel<<<H_NUM * NCH, 256, smem_attn>>>();
    gemm_mma<EPI_RES> <<<gD, 256>>>(attn, Wo, bo, x, x2, S_LEN, D_DIM, D_DIM);
    ln_kernel<<<S_LEN, 256>>>(x2, g2, be2, h2);
    gemm_mma<EPI_GELU><<<gF, 256>>>(h2, W1, b1, nullptr, ff, S_LEN, FF_DIM, D_DIM);
    gemm_mma<EPI_RES> <<<gD, 256>>>(ff, W2, b2, x2, out, S_LEN, D_DIM, FF_DIM);
}